// round 6
// baseline (speedup 1.0000x reference)
#include <cuda_runtime.h>
#include <math.h>

// Problem constants
#define T_SEQ 256
#define BATCH 64
#define HID   512
#define G4H   2048   // 4*H
#define D2H   1024   // 2*H
#define MR    (T_SEQ*BATCH)   // 16384 rows
#define NBLK_DIR 64

typedef unsigned long long u64;

// ---------------- scratch (device globals: allocation-free) ----------------
__device__ float g_gxf[(size_t)MR * G4H];
__device__ float g_gxb[(size_t)MR * G4H];
__device__ float g_bufA[(size_t)MR * D2H];
__device__ float g_bufB[(size_t)MR * D2H];
__device__ float g_bufC[(size_t)MR * D2H];
__device__ float g_h[2][2][BATCH * HID];    // [dir][pingpong][B*H]
__device__ float g_c[2][BATCH * HID];       // [dir][B*H]
__device__ unsigned g_bar[2];               // per-direction grid barrier counters

__device__ __forceinline__ float* sel_buf(int sel, float* ext) {
    switch (sel) {
        case 1: return g_bufA;
        case 2: return g_bufB;
        case 3: return g_bufC;
        case 4: return g_gxf;
        case 5: return g_gxb;
        default: return ext;
    }
}
__device__ __forceinline__ const float* sel_cbuf(int sel, const float* ext) {
    switch (sel) {
        case 1: return g_bufA;
        case 2: return g_bufB;
        case 3: return g_bufC;
        case 4: return g_gxf;
        case 5: return g_gxb;
        default: return ext;
    }
}

// ---------------- packed f32x2 helpers ----------------
__device__ __forceinline__ u64 pack2(float lo, float hi) {
    u64 r; asm("mov.b64 %0, {%1, %2};" : "=l"(r) : "f"(lo), "f"(hi)); return r;
}
__device__ __forceinline__ void unpack2(u64 v, float& lo, float& hi) {
    asm("mov.b64 {%0, %1}, %2;" : "=f"(lo), "=f"(hi) : "l"(v));
}
__device__ __forceinline__ void ffma2(u64& d, u64 a, u64 b) {
    asm("fma.rn.f32x2 %0, %1, %2, %0;" : "+l"(d) : "l"(a), "l"(b));
}
__device__ __forceinline__ u64 addf2(u64 a, u64 b) {
    u64 r; asm("add.rn.f32x2 %0, %1, %2;" : "=l"(r) : "l"(a), "l"(b)); return r;
}

__device__ __forceinline__ float sigf(float x) { return 1.f / (1.f + __expf(-x)); }

// ---------------- GEMM: C[M,N] = A[M,K] @ W[N,K]^T + bias ----------------
// FFMA2 microkernel: A tile stored DUPLICATED ((v,v) pairs) in smem so the
// inner loop is pure LDS.128 + fma.rn.f32x2 with no packing movs.
#define BMT 128
#define BNT 128
#define BKT 16
#define AST 264              // duplicated-A row stride (words), 16B-aligned
#define WST 132              // W row stride (words), 16B-aligned
#define GEMM_SMEM_BYTES ((2*BKT*AST + 2*BKT*WST) * 4)   // 50688 B

#define ASL(s,k,i) Asm[((s)*BKT + (k))*AST + (i)]
#define WSL(s,k,i) Wsm[((s)*BKT + (k))*WST + (i)]

// store prefetched tile: A duplicated (STS.64), W scalar
#define STS_TILE(s) do { \
    *(float2*)&ASL(s, lk+0, 2*lrow)       = make_float2(pa0.x, pa0.x); \
    *(float2*)&ASL(s, lk+1, 2*lrow)       = make_float2(pa0.y, pa0.y); \
    *(float2*)&ASL(s, lk+2, 2*lrow)       = make_float2(pa0.z, pa0.z); \
    *(float2*)&ASL(s, lk+3, 2*lrow)       = make_float2(pa0.w, pa0.w); \
    *(float2*)&ASL(s, lk+0, 2*(lrow+64))  = make_float2(pa1.x, pa1.x); \
    *(float2*)&ASL(s, lk+1, 2*(lrow+64))  = make_float2(pa1.y, pa1.y); \
    *(float2*)&ASL(s, lk+2, 2*(lrow+64))  = make_float2(pa1.z, pa1.z); \
    *(float2*)&ASL(s, lk+3, 2*(lrow+64))  = make_float2(pa1.w, pa1.w); \
    WSL(s, lk+0, lrow)    = pw0.x; WSL(s, lk+1, lrow)    = pw0.y; \
    WSL(s, lk+2, lrow)    = pw0.z; WSL(s, lk+3, lrow)    = pw0.w; \
    WSL(s, lk+0, lrow+64) = pw1.x; WSL(s, lk+1, lrow+64) = pw1.y; \
    WSL(s, lk+2, lrow+64) = pw1.z; WSL(s, lk+3, lrow+64) = pw1.w; } while (0)

template<int EPI>
__global__ __launch_bounds__(256, 2)
void gemm_kernel(const float* __restrict__ Aext, int aSel,
                 const float* __restrict__ W0, const float* __restrict__ W1,
                 const float* __restrict__ bias0, const float* __restrict__ bias1,
                 float* __restrict__ C0ext, int c0Sel,
                 float* __restrict__ C1ext, int c1Sel,
                 const float* __restrict__ prevExt, int prevSel,
                 int M, int N, int K)
{
    (void)M;
    const float* A    = sel_cbuf(aSel, Aext);
    const float* W    = blockIdx.z ? W1 : W0;
    const float* bias = blockIdx.z ? bias1 : bias0;
    float*       C    = blockIdx.z ? sel_buf(c1Sel, C1ext) : sel_buf(c0Sel, C0ext);

    extern __shared__ float gsm[];
    float* Asm = gsm;                    // [2][BKT][AST]
    float* Wsm = gsm + 2 * BKT * AST;    // [2][BKT][WST]

    const int tid = threadIdx.x;
    const int tx  = tid & 15;
    const int ty  = tid >> 4;
    const int m0  = blockIdx.y * BMT;
    const int n0  = blockIdx.x * BNT;
    const int lrow = tid >> 2;
    const int lk   = (tid & 3) << 2;

    const float* Ab = A + (size_t)(m0 + lrow) * K + lk;
    const float* Wb = W + (size_t)(n0 + lrow) * K + lk;
    const size_t rstep = (size_t)64 * K;

    float4 pa0, pa1, pw0, pw1;
    pa0 = *(const float4*)(Ab);
    pa1 = *(const float4*)(Ab + rstep);
    pw0 = *(const float4*)(Wb);
    pw1 = *(const float4*)(Wb + rstep);
    STS_TILE(0);
    __syncthreads();

    u64 acc[8][4] = {};   // [row i][col pair jp] packed (j=2jp, 2jp+1)
    const int nk = K / BKT;
    for (int kt = 0; kt < nk; kt++) {
        const int s = kt & 1;
        if (kt + 1 < nk) {
            const int off = (kt + 1) * BKT;
            pa0 = *(const float4*)(Ab + off);
            pa1 = *(const float4*)(Ab + rstep + off);
            pw0 = *(const float4*)(Wb + off);
            pw1 = *(const float4*)(Wb + rstep + off);
        }
        #pragma unroll
        for (int k = 0; k < BKT; k++) {
            // duplicated a-pairs: 4x LDS.128 -> 8 u64 dups
            ulonglong2 a01 = *(const ulonglong2*)&ASL(s, k, ty * 16 + 0);
            ulonglong2 a23 = *(const ulonglong2*)&ASL(s, k, ty * 16 + 4);
            ulonglong2 a45 = *(const ulonglong2*)&ASL(s, k, ty * 16 + 8);
            ulonglong2 a67 = *(const ulonglong2*)&ASL(s, k, ty * 16 + 12);
            // b natural pairs: 2x LDS.128 -> 4 u64 pairs
            ulonglong2 b03 = *(const ulonglong2*)&WSL(s, k, tx * 8);
            ulonglong2 b47 = *(const ulonglong2*)&WSL(s, k, tx * 8 + 4);
            u64 ad[8] = { a01.x, a01.y, a23.x, a23.y, a45.x, a45.y, a67.x, a67.y };
            u64 bp[4] = { b03.x, b03.y, b47.x, b47.y };
            #pragma unroll
            for (int i = 0; i < 8; i++)
                #pragma unroll
                for (int jp = 0; jp < 4; jp++)
                    ffma2(acc[i][jp], ad[i], bp[jp]);
        }
        if (kt + 1 < nk) STS_TILE(s ^ 1);
        __syncthreads();
    }

    float bj[8];
    #pragma unroll
    for (int j = 0; j < 8; j++) bj[j] = bias[n0 + tx * 8 + j];

    #pragma unroll
    for (int i = 0; i < 8; i++) {
        const int m = m0 + ty * 8 + i;
        float* crow = C + (size_t)m * N + n0 + tx * 8;
        float av[8];
        #pragma unroll
        for (int jp = 0; jp < 4; jp++)
            unpack2(acc[i][jp], av[2 * jp], av[2 * jp + 1]);
        float v[8];
        if (EPI == 0) {
            #pragma unroll
            for (int j = 0; j < 8; j++) v[j] = av[j] + bj[j];
        } else {
            const float* prev   = sel_cbuf(prevSel, prevExt);
            const float* catrow = A    + (size_t)m * K + n0 + tx * 8;  // K==N here
            const float* prow   = prev + (size_t)m * N + n0 + tx * 8;
            float4 c0 = *(const float4*)(catrow);
            float4 c1 = *(const float4*)(catrow + 4);
            float4 p0 = *(const float4*)(prow);
            float4 p1 = *(const float4*)(prow + 4);
            const float catv[8] = {c0.x,c0.y,c0.z,c0.w,c1.x,c1.y,c1.z,c1.w};
            const float prv[8]  = {p0.x,p0.y,p0.z,p0.w,p1.x,p1.y,p1.z,p1.w};
            #pragma unroll
            for (int j = 0; j < 8; j++) {
                float gsig = 1.f / (1.f + expf(-(av[j] + bj[j])));
                v[j] = gsig * catv[j] + (1.f - gsig) * prv[j];
            }
        }
        *(float4*)(crow)     = *(float4*)&v[0];
        *(float4*)(crow + 4) = *(float4*)&v[4];
    }
}

// ---------------- persistent LSTM recurrence (one launch per layer) --------
#define HS_ST   513
#define SM_W_FLOATS   (8 * HID * 4)                 // 16384 floats (64KB)
#define SM_H_FLOATS   (BATCH * HS_ST)               // 32832 floats
#define SM_RED_U64    (8 * 32 * 4)                  // 1024 u64 (8KB)
#define PERS_SMEM_BYTES ((SM_W_FLOATS + SM_H_FLOATS) * 4 + SM_RED_U64 * 8)

__global__ __launch_bounds__(512, 1)
void pers_lstm_kernel(const float* __restrict__ Whf, const float* __restrict__ Whb,
                      const float* __restrict__ masks,
                      const float* __restrict__ f_init, const float* __restrict__ b_init,
                      int layer, int outSel, float* __restrict__ outExt)
{
    extern __shared__ float smem[];
    float* wsm = smem;                               // [col][k][gate] float
    float* hs  = smem + SM_W_FLOATS;                 // [b*513 + k]
    u64*   red = (u64*)(smem + SM_W_FLOATS + SM_H_FLOATS);

    const int dir  = blockIdx.y;
    const float* Whh  = dir ? Whb : Whf;
    const float* gx   = dir ? g_gxb : g_gxf;
    const float* init = (dir ? b_init : f_init) + (size_t)layer * 2 * HID;
    float* outcat = sel_buf(outSel, outExt);

    const int tid  = threadIdx.x;
    const int lane = tid & 31;
    const int wid  = tid >> 5;
    const int hc0  = blockIdx.x * 8;

    const int kh  = wid >> 3;
    const int wlo = wid & 7;
    const int p   = wlo & 3;
    const int bh  = wlo >> 2;
    const int b   = bh * 32 + lane;
    const int hcol0 = hc0 + 2 * p;

    const int sb  = tid >> 3;
    const int skq = (tid & 7) << 2;

    #pragma unroll
    for (int c = 0; c < 8; c++)
        #pragma unroll
        for (int g = 0; g < 4; g++)
            wsm[((c << 9) + tid) * 4 + g] = Whh[(size_t)((g << 9) + hc0 + c) * HID + tid];

    float creg0 = init[HID + hcol0];
    float creg1 = init[HID + hcol0 + 1];
    __syncthreads();

    const ulonglong2* wq  = (const ulonglong2*)wsm;
    const ulonglong2* wq0 = wq + (2 * p) * HID;
    const ulonglong2* wq1 = wq + (2 * p + 1) * HID;
    const float* hrowc = hs + b * HS_ST;
    const int   k0 = kh * 256;

    for (int s = 0; s < T_SEQ; s++) {
        const int t = dir ? (T_SEQ - 1 - s) : s;
        const float* hin = g_h[dir][s & 1];
        float* hout      = g_h[dir][(s & 1) ^ 1];

        float2 gi, gf, gg, go; float mk = 0.f;
        if (kh == 0) {
            const size_t gb = ((size_t)t * BATCH + b) * G4H + hcol0;
            gi = __ldcg((const float2*)&gx[gb + 0 * HID]);
            gf = __ldcg((const float2*)&gx[gb + 1 * HID]);
            gg = __ldcg((const float2*)&gx[gb + 2 * HID]);
            go = __ldcg((const float2*)&gx[gb + 3 * HID]);
            mk = __ldg(&masks[t * BATCH + b]);
        }

        const float* hrow = hin + sb * HID + skq;
        float* hdstb = hs + sb * HS_ST + skq;
        #pragma unroll
        for (int half = 0; half < 2; half++) {
            float4 pf[8];
            #pragma unroll
            for (int i = 0; i < 8; i++)
                pf[i] = __ldcg((const float4*)(hrow + half * 256 + i * 32));
            #pragma unroll
            for (int i = 0; i < 8; i++) {
                float* d = hdstb + half * 256 + i * 32;
                d[0] = pf[i].x; d[1] = pf[i].y; d[2] = pf[i].z; d[3] = pf[i].w;
            }
        }
        __syncthreads();

        u64 a0 = 0, a1 = 0, a2 = 0, a3 = 0;
        #pragma unroll 8
        for (int k = k0; k < k0 + 256; k++) {
            ulonglong2 wa = wq0[k];
            ulonglong2 wb = wq1[k];
            float hv = hrowc[k];
            u64 hd = pack2(hv, hv);
            ffma2(a0, wa.x, hd);
            ffma2(a1, wa.y, hd);
            ffma2(a2, wb.x, hd);
            ffma2(a3, wb.y, hd);
        }

        if (kh == 1) {
            ulonglong2* r = (ulonglong2*)(red + (((wlo << 5) + lane) << 2));
            r[0] = make_ulonglong2(a0, a1);
            r[1] = make_ulonglong2(a2, a3);
        }
        __syncthreads();

        if (kh == 0) {
            const ulonglong2* r = (const ulonglong2*)(red + (((wlo << 5) + lane) << 2));
            ulonglong2 r0 = r[0], r1 = r[1];
            a0 = addf2(a0, r0.x); a1 = addf2(a1, r0.y);
            a2 = addf2(a2, r1.x); a3 = addf2(a3, r1.y);

            float pi0, pF0, pg0, po0, pi1, pF1, pg1, po1;
            unpack2(a0, pi0, pF0); unpack2(a1, pg0, po0);
            unpack2(a2, pi1, pF1); unpack2(a3, pg1, po1);

            float ig0 = sigf(pi0 + gi.x), fg0 = sigf(pF0 + gf.x);
            float tg0 = tanhf(pg0 + gg.x), og0 = sigf(po0 + go.x);
            float cn0 = (fg0 * creg0 + ig0 * tg0) * mk;
            float hn0 = og0 * tanhf(cn0) * mk;
            creg0 = cn0;

            float ig1 = sigf(pi1 + gi.y), fg1 = sigf(pF1 + gf.y);
            float tg1 = tanhf(pg1 + gg.y), og1 = sigf(po1 + go.y);
            float cn1 = (fg1 * creg1 + ig1 * tg1) * mk;
            float hn1 = og1 * tanhf(cn1) * mk;
            creg1 = cn1;

            float2 hv2 = make_float2(hn0, hn1);
            __stcg((float2*)&hout[b * HID + hcol0], hv2);
            __stcg((float2*)&outcat[(size_t)t * (BATCH * D2H) + (size_t)b * D2H
                                    + dir * HID + hcol0], hv2);
        }

        __threadfence();
        __syncthreads();
        if (tid == 0) {
            atomicAdd(&g_bar[dir], 1u);
            const unsigned target = (unsigned)NBLK_DIR * (unsigned)(s + 1);
            volatile unsigned* pb = &g_bar[dir];
            while (*pb < target) __nanosleep(32);
        }
        __syncthreads();
    }

    if (kh == 0)
        *(float2*)&g_c[dir][b * HID + hcol0] = make_float2(creg0, creg1);
}

// ---------------- small state kernels ----------------
__global__ void init_states_kernel(const float* __restrict__ f_init,
                                   const float* __restrict__ b_init, int layer)
{
    int idx = blockIdx.x * blockDim.x + threadIdx.x;
    if (idx < 2 && blockIdx.x == 0) g_bar[idx] = 0;
    if (idx >= BATCH * HID) return;
    int j = idx & (HID - 1);
    const float* fi = f_init + layer * 2 * HID;
    const float* bi = b_init + layer * 2 * HID;
    g_h[0][0][idx] = fi[j];
    g_c[0][idx]    = fi[HID + j];
    g_h[1][0][idx] = bi[j];
    g_c[1][idx]    = bi[HID + j];
}

__global__ void copy_states_kernel(float* __restrict__ hn, float* __restrict__ cn, int layer)
{
    int idx = blockIdx.x * blockDim.x + threadIdx.x;
    if (idx >= BATCH * HID) return;
    hn[(size_t)(2 * layer + 0) * BATCH * HID + idx] = g_h[0][0][idx];
    hn[(size_t)(2 * layer + 1) * BATCH * HID + idx] = g_h[1][0][idx];
    cn[(size_t)(2 * layer + 0) * BATCH * HID + idx] = g_c[0][idx];
    cn[(size_t)(2 * layer + 1) * BATCH * HID + idx] = g_c[1][idx];
}

// ---------------- launcher ----------------
extern "C" void kernel_launch(void* const* d_in, const int* in_sizes, int n_in,
                              void* d_out, int out_size)
{
    (void)in_sizes; (void)n_in; (void)out_size;
    const float* x          = (const float*)d_in[0];
    const float* masks      = (const float*)d_in[1];
    const float* f_Wih0     = (const float*)d_in[2];
    const float* f_Wih_rest = (const float*)d_in[3];
    const float* f_Whh      = (const float*)d_in[4];
    const float* f_b        = (const float*)d_in[5];
    const float* b_Wih0     = (const float*)d_in[6];
    const float* b_Wih_rest = (const float*)d_in[7];
    const float* b_Whh      = (const float*)d_in[8];
    const float* b_b        = (const float*)d_in[9];
    const float* f_init     = (const float*)d_in[10];
    const float* b_init     = (const float*)d_in[11];
    const float* proj_W     = (const float*)d_in[12];
    const float* proj_b     = (const float*)d_in[13];

    float* out = (float*)d_out;                       // [T,B,2H]
    float* hn  = out + (size_t)MR * D2H;              // [6,B,H]
    float* cn  = hn + (size_t)6 * BATCH * HID;        // [6,B,H]

    cudaFuncSetAttribute(pers_lstm_kernel,
                         cudaFuncAttributeMaxDynamicSharedMemorySize, PERS_SMEM_BYTES);
    cudaFuncSetAttribute(gemm_kernel<0>,
                         cudaFuncAttributeMaxDynamicSharedMemorySize, GEMM_SMEM_BYTES);
    cudaFuncSetAttribute(gemm_kernel<1>,
                         cudaFuncAttributeMaxDynamicSharedMemorySize, GEMM_SMEM_BYTES);

    const int layerInSel[3]  = { 0, 1, 3 };   // x, bufA, bufC
    const int catSel[3]      = { 1, 2, 1 };   // bufA, bufB, bufA
    const int Kin[3]         = { 512, 1024, 1024 };

    for (int layer = 0; layer < 3; layer++) {
        init_states_kernel<<<128, 256>>>(f_init, b_init, layer);

        const float* Wf = (layer == 0) ? f_Wih0 : f_Wih_rest + (size_t)(layer - 1) * G4H * D2H;
        const float* Wb = (layer == 0) ? b_Wih0 : b_Wih_rest + (size_t)(layer - 1) * G4H * D2H;
        dim3 ggrid(G4H / BNT, MR / BMT, 2);
        gemm_kernel<0><<<ggrid, 256, GEMM_SMEM_BYTES>>>(
            (layer == 0) ? x : nullptr, layerInSel[layer],
            Wf, Wb,
            f_b + (size_t)layer * G4H, b_b + (size_t)layer * G4H,
            nullptr, 4 /*gxf*/, nullptr, 5 /*gxb*/,
            nullptr, 0,
            MR, G4H, Kin[layer]);

        const float* Whf = f_Whh + (size_t)layer * G4H * HID;
        const float* Whb = b_Whh + (size_t)layer * G4H * HID;
        pers_lstm_kernel<<<dim3(NBLK_DIR, 2), 512, PERS_SMEM_BYTES>>>(
            Whf, Whb, masks, f_init, b_init, layer, catSel[layer], nullptr);

        copy_states_kernel<<<128, 256>>>(hn, cn, layer);

        if (layer > 0) {
            dim3 pgrid(D2H / BNT, MR / BMT, 1);
            gemm_kernel<1><<<pgrid, 256, GEMM_SMEM_BYTES>>>(
                nullptr, catSel[layer],
                proj_W + (size_t)(layer - 1) * D2H * D2H, nullptr,
                proj_b + (size_t)(layer - 1) * D2H, nullptr,
                (layer == 2) ? out : nullptr, (layer == 1) ? 3 : 0,
                nullptr, 0,
                nullptr, layerInSel[layer],
                MR, D2H, D2H);
        }
    }
}

// round 9
// speedup vs baseline: 1.4094x; 1.4094x over previous
#include <cuda_runtime.h>
#include <cuda_bf16.h>
#include <math.h>
#include <stdint.h>

// Problem constants
#define T_SEQ 256
#define BATCH 64
#define HID   512
#define G4H   2048   // 4*H
#define D2H   1024   // 2*H
#define MR    (T_SEQ*BATCH)   // 16384 rows
#define NBLK_DIR 64

typedef unsigned long long u64;

// ---------------- scratch (device globals: allocation-free) ----------------
__device__ float g_gxf[(size_t)MR * G4H];
__device__ float g_gxb[(size_t)MR * G4H];
__device__ float g_bufA[(size_t)MR * D2H];
__device__ float g_bufB[(size_t)MR * D2H];
__device__ float g_bufC[(size_t)MR * D2H];
__device__ float g_h[2][2][BATCH * HID];    // [dir][pingpong][B*H]
__device__ float g_c[2][BATCH * HID];       // [dir][B*H]
__device__ unsigned g_bar[2];               // per-direction grid barrier counters
// bf16 split scratch
__device__ __nv_bfloat16 g_Ahi[(size_t)MR * D2H];
__device__ __nv_bfloat16 g_Alo[(size_t)MR * D2H];
__device__ __nv_bfloat16 g_Whi[(size_t)2 * G4H * D2H];
__device__ __nv_bfloat16 g_Wlo[(size_t)2 * G4H * D2H];

__device__ __forceinline__ float* sel_buf(int sel, float* ext) {
    switch (sel) {
        case 1: return g_bufA;
        case 2: return g_bufB;
        case 3: return g_bufC;
        case 4: return g_gxf;
        case 5: return g_gxb;
        default: return ext;
    }
}
__device__ __forceinline__ const float* sel_cbuf(int sel, const float* ext) {
    switch (sel) {
        case 1: return g_bufA;
        case 2: return g_bufB;
        case 3: return g_bufC;
        case 4: return g_gxf;
        case 5: return g_gxb;
        default: return ext;
    }
}

// ---------------- packed f32x2 helpers (recurrence) ----------------
__device__ __forceinline__ u64 pack2(float lo, float hi) {
    u64 r; asm("mov.b64 %0, {%1, %2};" : "=l"(r) : "f"(lo), "f"(hi)); return r;
}
__device__ __forceinline__ void unpack2(u64 v, float& lo, float& hi) {
    asm("mov.b64 {%0, %1}, %2;" : "=f"(lo), "=f"(hi) : "l"(v));
}
__device__ __forceinline__ void ffma2(u64& d, u64 a, u64 b) {
    asm("fma.rn.f32x2 %0, %1, %2, %0;" : "+l"(d) : "l"(a), "l"(b));
}
__device__ __forceinline__ u64 addf2(u64 a, u64 b) {
    u64 r; asm("add.rn.f32x2 %0, %1, %2;" : "=l"(r) : "l"(a), "l"(b)); return r;
}
__device__ __forceinline__ float sigf(float x) { return 1.f / (1.f + __expf(-x)); }

// ---------------- bf16 mma.sync (sm_80+ PTX, HMMA on sm_100) --------------
__device__ __forceinline__ void mma16816(float* c, const uint32_t* a, const uint32_t* b)
{
    asm volatile(
        "mma.sync.aligned.m16n8k16.row.col.f32.bf16.bf16.f32 "
        "{%0,%1,%2,%3}, {%4,%5,%6,%7}, {%8,%9}, {%0,%1,%2,%3};"
        : "+f"(c[0]), "+f"(c[1]), "+f"(c[2]), "+f"(c[3])
        : "r"(a[0]), "r"(a[1]), "r"(a[2]), "r"(a[3]), "r"(b[0]), "r"(b[1]));
}

// ---------------- split-bf16 conversion ----------------
__global__ void split_convert(const float* __restrict__ srcExt, int srcSel,
                              int dstIsW, size_t dstOff, size_t n4)
{
    const float* src = sel_cbuf(srcSel, srcExt);
    __nv_bfloat16* hi = (dstIsW ? g_Whi : g_Ahi) + dstOff;
    __nv_bfloat16* lo = (dstIsW ? g_Wlo : g_Alo) + dstOff;
    size_t i = (size_t)blockIdx.x * blockDim.x + threadIdx.x;
    const size_t stride = (size_t)gridDim.x * blockDim.x;
    for (; i < n4; i += stride) {
        float4 x = *(const float4*)(src + 4 * i);
        __nv_bfloat16 h0 = __float2bfloat16(x.x);
        __nv_bfloat16 h1 = __float2bfloat16(x.y);
        __nv_bfloat16 h2 = __float2bfloat16(x.z);
        __nv_bfloat16 h3 = __float2bfloat16(x.w);
        __nv_bfloat16 l0 = __float2bfloat16(x.x - __bfloat162float(h0));
        __nv_bfloat16 l1 = __float2bfloat16(x.y - __bfloat162float(h1));
        __nv_bfloat16 l2 = __float2bfloat16(x.z - __bfloat162float(h2));
        __nv_bfloat16 l3 = __float2bfloat16(x.w - __bfloat162float(h3));
        __nv_bfloat162* hp = (__nv_bfloat162*)(hi + 4 * i);
        __nv_bfloat162* lp = (__nv_bfloat162*)(lo + 4 * i);
        hp[0] = __nv_bfloat162(h0, h1); hp[1] = __nv_bfloat162(h2, h3);
        lp[0] = __nv_bfloat162(l0, l1); lp[1] = __nv_bfloat162(l2, l3);
    }
}

// ---------------- split-bf16 tensor-core GEMM (mma.sync / HMMA) ------------
// C[M,N] = A[M,K] @ W[N,K]^T (+bias / highway epilogue); 128x128 block tile,
// 8 warps (4x2), warp tile 32x64, k-chunk 32 double-buffered in smem.
// D = Ahi*Whi + Ahi*Wlo + Alo*Whi (f32 accum; Alo*Wlo negligible).
#define MRS 40                      // smem row stride in bf16 (80B: conflict-free frags)
#define MTS (128 * MRS)             // elems per tile (5120)
#define MBUF (4 * MTS)              // Ahi,Alo,Whi,Wlo per buffer (20480 elems)
#define MG_SMEM (2 * MBUF * 2)      // bytes = 81920

template<int EPI>
__global__ __launch_bounds__(256, 1)
void mma_gemm(const float* __restrict__ bias0, const float* __restrict__ bias1,
              float* C0ext, int c0Sel, float* C1ext, int c1Sel,
              const float* __restrict__ catExt, int catSel,
              const float* __restrict__ prevExt, int prevSel,
              int N, int K)
{
    extern __shared__ __nv_bfloat16 msm[];
    const int tid  = threadIdx.x;
    const int wid  = tid >> 5;
    const int lane = tid & 31;
    const int z    = blockIdx.z;
    const int n0   = blockIdx.x * 128;
    const int m0   = blockIdx.y * 128;
    const float* bias = z ? bias1 : bias0;
    float* C = z ? sel_buf(c1Sel, C1ext) : sel_buf(c0Sel, C0ext);

    const __nv_bfloat16* srcs[4] = {
        g_Ahi + (size_t)m0 * K,
        g_Alo + (size_t)m0 * K,
        g_Whi + (size_t)z * N * K + (size_t)n0 * K,
        g_Wlo + (size_t)z * N * K + (size_t)n0 * K
    };

    const int mw = (wid >> 1) * 32;   // warp m offset within tile
    const int nw = (wid & 1) * 64;    // warp n offset within tile
    const int r  = lane >> 2;         // fragment row 0..7
    const int cq = (lane & 3) * 2;    // fragment col pair

    float acc[2][8][4] = {};

    const int lrow = tid >> 2;            // 0..63? no: tid/4 -> 0..63 for 256thr? tid>>2 = 0..63
    // global load role: per tile, 2 iters of (u = i*256 + tid): row=u>>2, colq=(u&3)*8
    uint4 v[8];
    #pragma unroll
    for (int t = 0; t < 4; t++)
        #pragma unroll
        for (int i = 0; i < 2; i++) {
            const int u = i * 256 + tid;
            v[t * 2 + i] = *(const uint4*)(srcs[t] + (size_t)(u >> 2) * K + ((u & 3) * 8));
        }
    #pragma unroll
    for (int t = 0; t < 4; t++)
        #pragma unroll
        for (int i = 0; i < 2; i++) {
            const int u = i * 256 + tid;
            *(uint4*)(msm + t * MTS + (u >> 2) * MRS + (u & 3) * 8) = v[t * 2 + i];
        }
    __syncthreads();

    const int nch = K >> 5;
    for (int ch = 0; ch < nch; ch++) {
        const int b = ch & 1;
        if (ch + 1 < nch) {
            const int koff = (ch + 1) << 5;
            #pragma unroll
            for (int t = 0; t < 4; t++)
                #pragma unroll
                for (int i = 0; i < 2; i++) {
                    const int u = i * 256 + tid;
                    v[t * 2 + i] = *(const uint4*)(srcs[t] + (size_t)(u >> 2) * K + koff + ((u & 3) * 8));
                }
        }
        const __nv_bfloat16* sb = msm + b * MBUF;
        #pragma unroll
        for (int s = 0; s < 2; s++) {
            const int kb = s * 16;
            uint32_t ahi[2][4], alo[2][4];
            #pragma unroll
            for (int mi = 0; mi < 2; mi++) {
                const __nv_bfloat16* ar = sb + (mw + mi * 16 + r) * MRS + kb + cq;
                ahi[mi][0] = *(const uint32_t*)(ar);
                ahi[mi][1] = *(const uint32_t*)(ar + 8 * MRS);
                ahi[mi][2] = *(const uint32_t*)(ar + 8);
                ahi[mi][3] = *(const uint32_t*)(ar + 8 * MRS + 8);
                const __nv_bfloat16* al = ar + MTS;
                alo[mi][0] = *(const uint32_t*)(al);
                alo[mi][1] = *(const uint32_t*)(al + 8 * MRS);
                alo[mi][2] = *(const uint32_t*)(al + 8);
                alo[mi][3] = *(const uint32_t*)(al + 8 * MRS + 8);
            }
            uint32_t bhi[8][2], blo[8][2];
            #pragma unroll
            for (int ni = 0; ni < 8; ni++) {
                const __nv_bfloat16* wr = sb + 2 * MTS + (nw + ni * 8 + r) * MRS + kb + cq;
                bhi[ni][0] = *(const uint32_t*)(wr);
                bhi[ni][1] = *(const uint32_t*)(wr + 8);
                const __nv_bfloat16* wl = wr + MTS;
                blo[ni][0] = *(const uint32_t*)(wl);
                blo[ni][1] = *(const uint32_t*)(wl + 8);
            }
            #pragma unroll
            for (int mi = 0; mi < 2; mi++)
                #pragma unroll
                for (int ni = 0; ni < 8; ni++) {
                    mma16816(acc[mi][ni], ahi[mi], bhi[ni]);
                    mma16816(acc[mi][ni], ahi[mi], blo[ni]);
                    mma16816(acc[mi][ni], alo[mi], bhi[ni]);
                }
        }
        if (ch + 1 < nch) {
            __nv_bfloat16* db = msm + ((ch + 1) & 1) * MBUF;
            #pragma unroll
            for (int t = 0; t < 4; t++)
                #pragma unroll
                for (int i = 0; i < 2; i++) {
                    const int u = i * 256 + tid;
                    *(uint4*)(db + t * MTS + (u >> 2) * MRS + (u & 3) * 8) = v[t * 2 + i];
                }
        }
        __syncthreads();
    }

    // ---- epilogue ----
    float2 bj[8];
    #pragma unroll
    for (int ni = 0; ni < 8; ni++)
        bj[ni] = *(const float2*)(bias + n0 + nw + ni * 8 + cq);

    #pragma unroll
    for (int mi = 0; mi < 2; mi++) {
        #pragma unroll
        for (int half = 0; half < 2; half++) {
            const int m = m0 + mw + mi * 16 + r + half * 8;
            float* crow = C + (size_t)m * N + n0 + nw;
            if (EPI == 0) {
                #pragma unroll
                for (int ni = 0; ni < 8; ni++) {
                    float2 o = make_float2(acc[mi][ni][half * 2 + 0] + bj[ni].x,
                                           acc[mi][ni][half * 2 + 1] + bj[ni].y);
                    *(float2*)(crow + ni * 8 + cq) = o;
                }
            } else {
                const float* catrow  = sel_cbuf(catSel, catExt)   + (size_t)m * N + n0 + nw;
                const float* prevrow = sel_cbuf(prevSel, prevExt) + (size_t)m * N + n0 + nw;
                #pragma unroll
                for (int ni = 0; ni < 8; ni++) {
                    float2 cv = *(const float2*)(catrow + ni * 8 + cq);
                    float2 pv = *(const float2*)(prevrow + ni * 8 + cq);
                    float g0 = 1.f / (1.f + expf(-(acc[mi][ni][half * 2 + 0] + bj[ni].x)));
                    float g1 = 1.f / (1.f + expf(-(acc[mi][ni][half * 2 + 1] + bj[ni].y)));
                    float2 o = make_float2(g0 * cv.x + (1.f - g0) * pv.x,
                                           g1 * cv.y + (1.f - g1) * pv.y);
                    *(float2*)(crow + ni * 8 + cq) = o;
                }
            }
        }
    }
    (void)lrow;
}

// ---------------- persistent LSTM recurrence (passing R4 version) ----------
#define HS_ST   513
#define SM_W_FLOATS   (8 * HID * 4)
#define SM_H_FLOATS   (BATCH * HS_ST)
#define SM_RED_U64    (8 * 32 * 4)
#define PERS_SMEM_BYTES ((SM_W_FLOATS + SM_H_FLOATS) * 4 + SM_RED_U64 * 8)

__global__ __launch_bounds__(512, 1)
void pers_lstm_kernel(const float* __restrict__ Whf, const float* __restrict__ Whb,
                      const float* __restrict__ masks,
                      const float* __restrict__ f_init, const float* __restrict__ b_init,
                      int layer, int outSel, float* __restrict__ outExt)
{
    extern __shared__ float smem[];
    float* wsm = smem;
    float* hs  = smem + SM_W_FLOATS;
    u64*   red = (u64*)(smem + SM_W_FLOATS + SM_H_FLOATS);

    const int dir  = blockIdx.y;
    const float* Whh  = dir ? Whb : Whf;
    const float* gx   = dir ? g_gxb : g_gxf;
    const float* init = (dir ? b_init : f_init) + (size_t)layer * 2 * HID;
    float* outcat = sel_buf(outSel, outExt);

    const int tid  = threadIdx.x;
    const int lane = tid & 31;
    const int wid  = tid >> 5;
    const int hc0  = blockIdx.x * 8;

    const int kh  = wid >> 3;
    const int wlo = wid & 7;
    const int p   = wlo & 3;
    const int bh  = wlo >> 2;
    const int b   = bh * 32 + lane;
    const int hcol0 = hc0 + 2 * p;

    const int sb  = tid >> 3;
    const int skq = (tid & 7) << 2;

    #pragma unroll
    for (int c = 0; c < 8; c++)
        #pragma unroll
        for (int g = 0; g < 4; g++)
            wsm[((c << 9) + tid) * 4 + g] = Whh[(size_t)((g << 9) + hc0 + c) * HID + tid];

    float creg0 = init[HID + hcol0];
    float creg1 = init[HID + hcol0 + 1];
    __syncthreads();

    const ulonglong2* wq  = (const ulonglong2*)wsm;
    const ulonglong2* wq0 = wq + (2 * p) * HID;
    const ulonglong2* wq1 = wq + (2 * p + 1) * HID;
    const float* hrowc = hs + b * HS_ST;
    const int   k0 = kh * 256;

    for (int s = 0; s < T_SEQ; s++) {
        const int t = dir ? (T_SEQ - 1 - s) : s;
        const float* hin = g_h[dir][s & 1];
        float* hout      = g_h[dir][(s & 1) ^ 1];

        float2 gi, gf, gg, go; float mk = 0.f;
        if (kh == 0) {
            const size_t gb = ((size_t)t * BATCH + b) * G4H + hcol0;
            gi = __ldcg((const float2*)&gx[gb + 0 * HID]);
            gf = __ldcg((const float2*)&gx[gb + 1 * HID]);
            gg = __ldcg((const float2*)&gx[gb + 2 * HID]);
            go = __ldcg((const float2*)&gx[gb + 3 * HID]);
            mk = __ldg(&masks[t * BATCH + b]);
        }

        const float* hrow = hin + sb * HID + skq;
        float* hdstb = hs + sb * HS_ST + skq;
        #pragma unroll
        for (int half = 0; half < 2; half++) {
            float4 pf[8];
            #pragma unroll
            for (int i = 0; i < 8; i++)
                pf[i] = __ldcg((const float4*)(hrow + half * 256 + i * 32));
            #pragma unroll
            for (int i = 0; i < 8; i++) {
                float* d = hdstb + half * 256 + i * 32;
                d[0] = pf[i].x; d[1] = pf[i].y; d[2] = pf[i].z; d[3] = pf[i].w;
            }
        }
        __syncthreads();

        u64 a0 = 0, a1 = 0, a2 = 0, a3 = 0;
        #pragma unroll 8
        for (int k = k0; k < k0 + 256; k++) {
            ulonglong2 wa = wq0[k];
            ulonglong2 wb = wq1[k];
            float hv = hrowc[k];
            u64 hd = pack2(hv, hv);
            ffma2(a0, wa.x, hd);
            ffma2(a1, wa.y, hd);
            ffma2(a2, wb.x, hd);
            ffma2(a3, wb.y, hd);
        }

        if (kh == 1) {
            ulonglong2* rr = (ulonglong2*)(red + (((wlo << 5) + lane) << 2));
            rr[0] = make_ulonglong2(a0, a1);
            rr[1] = make_ulonglong2(a2, a3);
        }
        __syncthreads();

        if (kh == 0) {
            const ulonglong2* rr = (const ulonglong2*)(red + (((wlo << 5) + lane) << 2));
            ulonglong2 r0 = rr[0], r1 = rr[1];
            a0 = addf2(a0, r0.x); a1 = addf2(a1, r0.y);
            a2 = addf2(a2, r1.x); a3 = addf2(a3, r1.y);

            float pi0, pF0, pg0, po0, pi1, pF1, pg1, po1;
            unpack2(a0, pi0, pF0); unpack2(a1, pg0, po0);
            unpack2(a2, pi1, pF1); unpack2(a3, pg1, po1);

            float ig0 = sigf(pi0 + gi.x), fg0 = sigf(pF0 + gf.x);
            float tg0 = tanhf(pg0 + gg.x), og0 = sigf(po0 + go.x);
            float cn0 = (fg0 * creg0 + ig0 * tg0) * mk;
            float hn0 = og0 * tanhf(cn0) * mk;
            creg0 = cn0;

            float ig1 = sigf(pi1 + gi.y), fg1 = sigf(pF1 + gf.y);
            float tg1 = tanhf(pg1 + gg.y), og1 = sigf(po1 + go.y);
            float cn1 = (fg1 * creg1 + ig1 * tg1) * mk;
            float hn1 = og1 * tanhf(cn1) * mk;
            creg1 = cn1;

            float2 hv2 = make_float2(hn0, hn1);
            __stcg((float2*)&hout[b * HID + hcol0], hv2);
            __stcg((float2*)&outcat[(size_t)t * (BATCH * D2H) + (size_t)b * D2H
                                    + dir * HID + hcol0], hv2);
        }

        __threadfence();
        __syncthreads();
        if (tid == 0) {
            atomicAdd(&g_bar[dir], 1u);
            const unsigned target = (unsigned)NBLK_DIR * (unsigned)(s + 1);
            volatile unsigned* pb = &g_bar[dir];
            while (*pb < target) __nanosleep(32);
        }
        __syncthreads();
    }

    if (kh == 0)
        *(float2*)&g_c[dir][b * HID + hcol0] = make_float2(creg0, creg1);
}

// ---------------- small state kernels ----------------
__global__ void init_states_kernel(const float* __restrict__ f_init,
                                   const float* __restrict__ b_init, int layer)
{
    int idx = blockIdx.x * blockDim.x + threadIdx.x;
    if (idx < 2 && blockIdx.x == 0) g_bar[idx] = 0;
    if (idx >= BATCH * HID) return;
    int j = idx & (HID - 1);
    const float* fi = f_init + layer * 2 * HID;
    const float* bi = b_init + layer * 2 * HID;
    g_h[0][0][idx] = fi[j];
    g_c[0][idx]    = fi[HID + j];
    g_h[1][0][idx] = bi[j];
    g_c[1][idx]    = bi[HID + j];
}

__global__ void copy_states_kernel(float* __restrict__ hn, float* __restrict__ cn, int layer)
{
    int idx = blockIdx.x * blockDim.x + threadIdx.x;
    if (idx >= BATCH * HID) return;
    hn[(size_t)(2 * layer + 0) * BATCH * HID + idx] = g_h[0][0][idx];
    hn[(size_t)(2 * layer + 1) * BATCH * HID + idx] = g_h[1][0][idx];
    cn[(size_t)(2 * layer + 0) * BATCH * HID + idx] = g_c[0][idx];
    cn[(size_t)(2 * layer + 1) * BATCH * HID + idx] = g_c[1][idx];
}

// ---------------- launcher ----------------
extern "C" void kernel_launch(void* const* d_in, const int* in_sizes, int n_in,
                              void* d_out, int out_size)
{
    (void)in_sizes; (void)n_in; (void)out_size;
    const float* x          = (const float*)d_in[0];
    const float* masks      = (const float*)d_in[1];
    const float* f_Wih0     = (const float*)d_in[2];
    const float* f_Wih_rest = (const float*)d_in[3];
    const float* f_Whh      = (const float*)d_in[4];
    const float* f_b        = (const float*)d_in[5];
    const float* b_Wih0     = (const float*)d_in[6];
    const float* b_Wih_rest = (const float*)d_in[7];
    const float* b_Whh      = (const float*)d_in[8];
    const float* b_b        = (const float*)d_in[9];
    const float* f_init     = (const float*)d_in[10];
    const float* b_init     = (const float*)d_in[11];
    const float* proj_W     = (const float*)d_in[12];
    const float* proj_b     = (const float*)d_in[13];

    float* out = (float*)d_out;                       // [T,B,2H]
    float* hn  = out + (size_t)MR * D2H;              // [6,B,H]
    float* cn  = hn + (size_t)6 * BATCH * HID;        // [6,B,H]

    cudaFuncSetAttribute(pers_lstm_kernel,
                         cudaFuncAttributeMaxDynamicSharedMemorySize, PERS_SMEM_BYTES);
    cudaFuncSetAttribute(mma_gemm<0>,
                         cudaFuncAttributeMaxDynamicSharedMemorySize, MG_SMEM);
    cudaFuncSetAttribute(mma_gemm<1>,
                         cudaFuncAttributeMaxDynamicSharedMemorySize, MG_SMEM);

    const int layerInSel[3]  = { 0, 1, 3 };   // x, bufA, bufC
    const int catSel[3]      = { 1, 2, 1 };   // bufA, bufB, bufA
    const int Kin[3]         = { 512, 1024, 1024 };

    for (int layer = 0; layer < 3; layer++) {
        const int K = Kin[layer];
        init_states_kernel<<<128, 256>>>(f_init, b_init, layer);

        // ---- split-convert gate GEMM operands ----
        split_convert<<<1024, 256>>>((layer == 0) ? x : nullptr, layerInSel[layer],
                                     0, 0, ((size_t)MR * K) / 4);
        const float* Wf = (layer == 0) ? f_Wih0 : f_Wih_rest + (size_t)(layer - 1) * G4H * D2H;
        const float* Wb = (layer == 0) ? b_Wih0 : b_Wih_rest + (size_t)(layer - 1) * G4H * D2H;
        split_convert<<<512, 256>>>(Wf, 0, 1, 0,                 ((size_t)G4H * K) / 4);
        split_convert<<<512, 256>>>(Wb, 0, 1, (size_t)G4H * K,   ((size_t)G4H * K) / 4);

        // ---- gate pre-activations via tensor-core GEMM ----
        mma_gemm<0><<<dim3(G4H / 128, MR / 128, 2), 256, MG_SMEM>>>(
            f_b + (size_t)layer * G4H, b_b + (size_t)layer * G4H,
            nullptr, 4 /*gxf*/, nullptr, 5 /*gxb*/,
            nullptr, 0, nullptr, 0,
            G4H, K);

        // ---- recurrence ----
        const float* Whf = f_Whh + (size_t)layer * G4H * HID;
        const float* Whb = b_Whh + (size_t)layer * G4H * HID;
        pers_lstm_kernel<<<dim3(NBLK_DIR, 2), 512, PERS_SMEM_BYTES>>>(
            Whf, Whb, masks, f_init, b_init, layer, catSel[layer], nullptr);

        copy_states_kernel<<<128, 256>>>(hn, cn, layer);

        // ---- highway projection ----
        if (layer > 0) {
            split_convert<<<1024, 256>>>(nullptr, catSel[layer], 0, 0, ((size_t)MR * D2H) / 4);
            split_convert<<<512, 256>>>(proj_W + (size_t)(layer - 1) * D2H * D2H, 0,
                                        1, 0, ((size_t)D2H * D2H) / 4);
            mma_gemm<1><<<dim3(D2H / 128, MR / 128, 1), 256, MG_SMEM>>>(
                proj_b + (size_t)(layer - 1) * D2H, nullptr,
                (layer == 2) ? out : nullptr, (layer == 1) ? 3 : 0,
                nullptr, 0,
                nullptr, catSel[layer],
                nullptr, layerInSel[layer],
                D2H, D2H);
        }
    }
}

// round 11
// speedup vs baseline: 2.2820x; 1.6191x over previous
#include <cuda_runtime.h>
#include <cuda_bf16.h>
#include <math.h>
#include <stdint.h>

// Problem constants
#define T_SEQ 256
#define BATCH 64
#define HID   512
#define G4H   2048   // 4*H
#define D2H   1024   // 2*H
#define MR    (T_SEQ*BATCH)   // 16384 rows
#define NBLK_DIR 64

typedef unsigned long long u64;

// ---------------- scratch (device globals: allocation-free) ----------------
__device__ float g_gxf[(size_t)MR * G4H];
__device__ float g_gxb[(size_t)MR * G4H];
__device__ float g_bufA[(size_t)MR * D2H];
__device__ float g_bufB[(size_t)MR * D2H];
__device__ float g_bufC[(size_t)MR * D2H];
__device__ float g_c[2][BATCH * HID];       // [dir][B*H]
__device__ unsigned g_bar[2];               // per-direction grid barrier counters
// bf16 h ping-pong: [dir][pingpong][hi/lo][B*H]
__device__ __nv_bfloat16 g_hbf[2][2][2][BATCH * HID];
// bf16 split scratch for GEMM operands
__device__ __nv_bfloat16 g_Ahi[(size_t)MR * D2H];
__device__ __nv_bfloat16 g_Alo[(size_t)MR * D2H];
__device__ __nv_bfloat16 g_Whi[(size_t)2 * G4H * D2H];
__device__ __nv_bfloat16 g_Wlo[(size_t)2 * G4H * D2H];

__device__ __forceinline__ float* sel_buf(int sel, float* ext) {
    switch (sel) {
        case 1: return g_bufA;
        case 2: return g_bufB;
        case 3: return g_bufC;
        case 4: return g_gxf;
        case 5: return g_gxb;
        default: return ext;
    }
}
__device__ __forceinline__ const float* sel_cbuf(int sel, const float* ext) {
    switch (sel) {
        case 1: return g_bufA;
        case 2: return g_bufB;
        case 3: return g_bufC;
        case 4: return g_gxf;
        case 5: return g_gxb;
        default: return ext;
    }
}

__device__ __forceinline__ float sigf(float x) { return 1.f / (1.f + __expf(-x)); }

// ---------------- bf16 mma.sync (sm_80+ PTX, HMMA on sm_100) --------------
__device__ __forceinline__ void mma16816(float* c, const uint32_t* a, const uint32_t* b)
{
    asm volatile(
        "mma.sync.aligned.m16n8k16.row.col.f32.bf16.bf16.f32 "
        "{%0,%1,%2,%3}, {%4,%5,%6,%7}, {%8,%9}, {%0,%1,%2,%3};"
        : "+f"(c[0]), "+f"(c[1]), "+f"(c[2]), "+f"(c[3])
        : "r"(a[0]), "r"(a[1]), "r"(a[2]), "r"(a[3]), "r"(b[0]), "r"(b[1]));
}

// ---------------- split-bf16 conversion ----------------
__global__ void split_convert(const float* __restrict__ srcExt, int srcSel,
                              int dstIsW, size_t dstOff, size_t n4)
{
    const float* src = sel_cbuf(srcSel, srcExt);
    __nv_bfloat16* hi = (dstIsW ? g_Whi : g_Ahi) + dstOff;
    __nv_bfloat16* lo = (dstIsW ? g_Wlo : g_Alo) + dstOff;
    size_t i = (size_t)blockIdx.x * blockDim.x + threadIdx.x;
    const size_t stride = (size_t)gridDim.x * blockDim.x;
    for (; i < n4; i += stride) {
        float4 x = *(const float4*)(src + 4 * i);
        __nv_bfloat16 h0 = __float2bfloat16(x.x);
        __nv_bfloat16 h1 = __float2bfloat16(x.y);
        __nv_bfloat16 h2 = __float2bfloat16(x.z);
        __nv_bfloat16 h3 = __float2bfloat16(x.w);
        __nv_bfloat16 l0 = __float2bfloat16(x.x - __bfloat162float(h0));
        __nv_bfloat16 l1 = __float2bfloat16(x.y - __bfloat162float(h1));
        __nv_bfloat16 l2 = __float2bfloat16(x.z - __bfloat162float(h2));
        __nv_bfloat16 l3 = __float2bfloat16(x.w - __bfloat162float(h3));
        __nv_bfloat162* hp = (__nv_bfloat162*)(hi + 4 * i);
        __nv_bfloat162* lp = (__nv_bfloat162*)(lo + 4 * i);
        hp[0] = __nv_bfloat162(h0, h1); hp[1] = __nv_bfloat162(h2, h3);
        lp[0] = __nv_bfloat162(l0, l1); lp[1] = __nv_bfloat162(l2, l3);
    }
}

// ---------------- split-bf16 tensor-core GEMM (R9, passing) ----------------
#define MRS 40
#define MTS (128 * MRS)
#define MBUF (4 * MTS)
#define MG_SMEM (2 * MBUF * 2)

template<int EPI>
__global__ __launch_bounds__(256, 1)
void mma_gemm(const float* __restrict__ bias0, const float* __restrict__ bias1,
              float* C0ext, int c0Sel, float* C1ext, int c1Sel,
              const float* __restrict__ catExt, int catSel,
              const float* __restrict__ prevExt, int prevSel,
              int N, int K)
{
    extern __shared__ __nv_bfloat16 msm[];
    const int tid  = threadIdx.x;
    const int wid  = tid >> 5;
    const int lane = tid & 31;
    const int z    = blockIdx.z;
    const int n0   = blockIdx.x * 128;
    const int m0   = blockIdx.y * 128;
    const float* bias = z ? bias1 : bias0;
    float* C = z ? sel_buf(c1Sel, C1ext) : sel_buf(c0Sel, C0ext);

    const __nv_bfloat16* srcs[4] = {
        g_Ahi + (size_t)m0 * K,
        g_Alo + (size_t)m0 * K,
        g_Whi + (size_t)z * N * K + (size_t)n0 * K,
        g_Wlo + (size_t)z * N * K + (size_t)n0 * K
    };

    const int mw = (wid >> 1) * 32;
    const int nw = (wid & 1) * 64;
    const int r  = lane >> 2;
    const int cq = (lane & 3) * 2;

    float acc[2][8][4] = {};

    uint4 v[8];
    #pragma unroll
    for (int t = 0; t < 4; t++)
        #pragma unroll
        for (int i = 0; i < 2; i++) {
            const int u = i * 256 + tid;
            v[t * 2 + i] = *(const uint4*)(srcs[t] + (size_t)(u >> 2) * K + ((u & 3) * 8));
        }
    #pragma unroll
    for (int t = 0; t < 4; t++)
        #pragma unroll
        for (int i = 0; i < 2; i++) {
            const int u = i * 256 + tid;
            *(uint4*)(msm + t * MTS + (u >> 2) * MRS + (u & 3) * 8) = v[t * 2 + i];
        }
    __syncthreads();

    const int nch = K >> 5;
    for (int ch = 0; ch < nch; ch++) {
        const int b = ch & 1;
        if (ch + 1 < nch) {
            const int koff = (ch + 1) << 5;
            #pragma unroll
            for (int t = 0; t < 4; t++)
                #pragma unroll
                for (int i = 0; i < 2; i++) {
                    const int u = i * 256 + tid;
                    v[t * 2 + i] = *(const uint4*)(srcs[t] + (size_t)(u >> 2) * K + koff + ((u & 3) * 8));
                }
        }
        const __nv_bfloat16* sb = msm + b * MBUF;
        #pragma unroll
        for (int s = 0; s < 2; s++) {
            const int kb = s * 16;
            uint32_t ahi[2][4], alo[2][4];
            #pragma unroll
            for (int mi = 0; mi < 2; mi++) {
                const __nv_bfloat16* ar = sb + (mw + mi * 16 + r) * MRS + kb + cq;
                ahi[mi][0] = *(const uint32_t*)(ar);
                ahi[mi][1] = *(const uint32_t*)(ar + 8 * MRS);
                ahi[mi][2] = *(const uint32_t*)(ar + 8);
                ahi[mi][3] = *(const uint32_t*)(ar + 8 * MRS + 8);
                const __nv_bfloat16* al = ar + MTS;
                alo[mi][0] = *(const uint32_t*)(al);
                alo[mi][1] = *(const uint32_t*)(al + 8 * MRS);
                alo[mi][2] = *(const uint32_t*)(al + 8);
                alo[mi][3] = *(const uint32_t*)(al + 8 * MRS + 8);
            }
            uint32_t bhi[8][2], blo[8][2];
            #pragma unroll
            for (int ni = 0; ni < 8; ni++) {
                const __nv_bfloat16* wr = sb + 2 * MTS + (nw + ni * 8 + r) * MRS + kb + cq;
                bhi[ni][0] = *(const uint32_t*)(wr);
                bhi[ni][1] = *(const uint32_t*)(wr + 8);
                const __nv_bfloat16* wl = wr + MTS;
                blo[ni][0] = *(const uint32_t*)(wl);
                blo[ni][1] = *(const uint32_t*)(wl + 8);
            }
            #pragma unroll
            for (int mi = 0; mi < 2; mi++)
                #pragma unroll
                for (int ni = 0; ni < 8; ni++) {
                    mma16816(acc[mi][ni], ahi[mi], bhi[ni]);
                    mma16816(acc[mi][ni], ahi[mi], blo[ni]);
                    mma16816(acc[mi][ni], alo[mi], bhi[ni]);
                }
        }
        if (ch + 1 < nch) {
            __nv_bfloat16* db = msm + ((ch + 1) & 1) * MBUF;
            #pragma unroll
            for (int t = 0; t < 4; t++)
                #pragma unroll
                for (int i = 0; i < 2; i++) {
                    const int u = i * 256 + tid;
                    *(uint4*)(db + t * MTS + (u >> 2) * MRS + (u & 3) * 8) = v[t * 2 + i];
                }
        }
        __syncthreads();
    }

    float2 bj[8];
    #pragma unroll
    for (int ni = 0; ni < 8; ni++)
        bj[ni] = *(const float2*)(bias + n0 + nw + ni * 8 + cq);

    #pragma unroll
    for (int mi = 0; mi < 2; mi++) {
        #pragma unroll
        for (int half = 0; half < 2; half++) {
            const int m = m0 + mw + mi * 16 + r + half * 8;
            float* crow = C + (size_t)m * N + n0 + nw;
            if (EPI == 0) {
                #pragma unroll
                for (int ni = 0; ni < 8; ni++) {
                    float2 o = make_float2(acc[mi][ni][half * 2 + 0] + bj[ni].x,
                                           acc[mi][ni][half * 2 + 1] + bj[ni].y);
                    *(float2*)(crow + ni * 8 + cq) = o;
                }
            } else {
                const float* catrow  = sel_cbuf(catSel, catExt)   + (size_t)m * N + n0 + nw;
                const float* prevrow = sel_cbuf(prevSel, prevExt) + (size_t)m * N + n0 + nw;
                #pragma unroll
                for (int ni = 0; ni < 8; ni++) {
                    float2 cv = *(const float2*)(catrow + ni * 8 + cq);
                    float2 pv = *(const float2*)(prevrow + ni * 8 + cq);
                    float g0 = 1.f / (1.f + expf(-(acc[mi][ni][half * 2 + 0] + bj[ni].x)));
                    float g1 = 1.f / (1.f + expf(-(acc[mi][ni][half * 2 + 1] + bj[ni].y)));
                    float2 o = make_float2(g0 * cv.x + (1.f - g0) * pv.x,
                                           g1 * cv.y + (1.f - g1) * pv.y);
                    *(float2*)(crow + ni * 8 + cq) = o;
                }
            }
        }
    }
}

// ---------------- persistent tensor-core LSTM recurrence -------------------
// grid (64, 2), 256 threads. Block = 8 hidden cols x 4 gates (N=32), M=64.
// 8 warps = 4 m-tiles x 2 k-halves. Whh split-bf16 in smem (once/layer);
// h exchanged via global bf16 hi/lo ping-pong; c in registers.
#define RWS 520                                  // smem row stride (bf16)
#define RH_ELE (64 * RWS)                        // one h buffer (33280 elems)
#define W_ELE  (32 * RWS)                        // one weight buffer
#define RED_OFF_ELE (2 * RH_ELE + 2 * W_ELE)     // 99840 elems
#define PERS2_SMEM (RED_OFF_ELE * 2 + 8192)      // 207872 B

__global__ __launch_bounds__(256, 1)
void pers_lstm2(const float* __restrict__ Whf, const float* __restrict__ Whb,
                const float* __restrict__ masks,
                const float* __restrict__ f_init, const float* __restrict__ b_init,
                int layer, int outSel, float* __restrict__ outExt)
{
    extern __shared__ __nv_bfloat16 sm2[];
    __nv_bfloat16* hhi = sm2;
    __nv_bfloat16* hlo = sm2 + RH_ELE;
    __nv_bfloat16* whi = sm2 + 2 * RH_ELE;
    __nv_bfloat16* wlo = whi + W_ELE;
    float* red = (float*)(sm2 + RED_OFF_ELE);

    const int dir = blockIdx.y;
    const float* Whh  = dir ? Whb : Whf;
    const float* gx   = dir ? g_gxb : g_gxf;
    const float* init = (dir ? b_init : f_init) + (size_t)layer * 2 * HID;
    float* outcat = sel_buf(outSel, outExt);

    const int tid = threadIdx.x, lane = tid & 31, wid = tid >> 5;
    const int kh = wid >> 2, mt = wid & 3;
    const int r = lane >> 2, cq = (lane & 3) * 2;
    const int hc0 = blockIdx.x * 8;

    // load + split Whh slice: smem row n = gate*8 + c  <-  Whh[gate*512+hc0+c][:]
    for (int n = 0; n < 32; n++) {
        const float* src = Whh + (size_t)((n >> 3) * HID + hc0 + (n & 7)) * HID;
        for (int k = tid; k < HID; k += 256) {
            float vv = src[k];
            __nv_bfloat16 h = __float2bfloat16(vv);
            whi[n * RWS + k] = h;
            wlo[n * RWS + k] = __float2bfloat16(vv - __bfloat162float(h));
        }
    }

    const int b0 = mt * 16 + r, b1 = b0 + 8;
    const int hcol = hc0 + cq;
    float creg[4];  // (b0,c0),(b0,c1),(b1,c0),(b1,c1)
    creg[0] = init[HID + hcol]; creg[1] = init[HID + hcol + 1];
    creg[2] = creg[0]; creg[3] = creg[1];
    __syncthreads();

    for (int s = 0; s < T_SEQ; s++) {
        const int t = dir ? (T_SEQ - 1 - s) : s;
        const uint4* ghi = (const uint4*)g_hbf[dir][s & 1][0];
        const uint4* glo = (const uint4*)g_hbf[dir][s & 1][1];

        float2 gxv[4][2]; float mk0 = 0.f, mk1 = 0.f;
        if (kh == 0) {
            const size_t gb0 = ((size_t)t * BATCH + b0) * G4H + hcol;
            const size_t gb1 = ((size_t)t * BATCH + b1) * G4H + hcol;
            #pragma unroll
            for (int g = 0; g < 4; g++) {
                gxv[g][0] = __ldcg((const float2*)&gx[gb0 + g * HID]);
                gxv[g][1] = __ldcg((const float2*)&gx[gb1 + g * HID]);
            }
            mk0 = __ldg(&masks[t * BATCH + b0]);
            mk1 = __ldg(&masks[t * BATCH + b1]);
        }

        // stage h hi/lo into smem (coalesced LDG.128, phase-conflict-free STS)
        #pragma unroll
        for (int i = 0; i < 16; i += 4) {
            uint4 va[4], vb[4];
            #pragma unroll
            for (int j = 0; j < 4; j++) {
                const int u = (i + j) * 256 + tid;
                va[j] = __ldcg(ghi + u);
                vb[j] = __ldcg(glo + u);
            }
            #pragma unroll
            for (int j = 0; j < 4; j++) {
                const int u = (i + j) * 256 + tid;
                const int row = u >> 6, c16 = u & 63;
                *(uint4*)(hhi + row * RWS + c16 * 8) = va[j];
                *(uint4*)(hlo + row * RWS + c16 * 8) = vb[j];
            }
        }
        __syncthreads();

        float acc[4][4] = {};
        const int k0 = kh * 256;
        #pragma unroll 4
        for (int ks = 0; ks < 16; ks++) {
            const int kb = k0 + ks * 16;
            const __nv_bfloat16* ar = hhi + (mt * 16 + r) * RWS + kb + cq;
            const __nv_bfloat16* al = hlo + (mt * 16 + r) * RWS + kb + cq;
            uint32_t ahi4[4], alo4[4];
            ahi4[0] = *(const uint32_t*)(ar);
            ahi4[1] = *(const uint32_t*)(ar + 8 * RWS);
            ahi4[2] = *(const uint32_t*)(ar + 8);
            ahi4[3] = *(const uint32_t*)(ar + 8 * RWS + 8);
            alo4[0] = *(const uint32_t*)(al);
            alo4[1] = *(const uint32_t*)(al + 8 * RWS);
            alo4[2] = *(const uint32_t*)(al + 8);
            alo4[3] = *(const uint32_t*)(al + 8 * RWS + 8);
            #pragma unroll
            for (int nt = 0; nt < 4; nt++) {
                const __nv_bfloat16* br = whi + (nt * 8 + r) * RWS + kb + cq;
                const __nv_bfloat16* bl = wlo + (nt * 8 + r) * RWS + kb + cq;
                uint32_t bhi2[2], blo2[2];
                bhi2[0] = *(const uint32_t*)(br); bhi2[1] = *(const uint32_t*)(br + 8);
                blo2[0] = *(const uint32_t*)(bl); blo2[1] = *(const uint32_t*)(bl + 8);
                mma16816(acc[nt], ahi4, bhi2);
                mma16816(acc[nt], ahi4, blo2);
                mma16816(acc[nt], alo4, bhi2);
            }
        }

        if (kh == 1) {
            float4* rr = (float4*)red + ((mt << 5) + lane) * 4;
            #pragma unroll
            for (int nt = 0; nt < 4; nt++)
                rr[nt] = make_float4(acc[nt][0], acc[nt][1], acc[nt][2], acc[nt][3]);
        }
        __syncthreads();

        if (kh == 0) {
            const float4* rr = (const float4*)red + ((mt << 5) + lane) * 4;
            #pragma unroll
            for (int nt = 0; nt < 4; nt++) {
                float4 rv = rr[nt];
                acc[nt][0] += rv.x; acc[nt][1] += rv.y;
                acc[nt][2] += rv.z; acc[nt][3] += rv.w;
            }
            float hn[4];
            #pragma unroll
            for (int j = 0; j < 4; j++) {
                const int bi = j >> 1;
                const float gxi = (j & 1) ? gxv[0][bi].y : gxv[0][bi].x;
                const float gxF = (j & 1) ? gxv[1][bi].y : gxv[1][bi].x;
                const float gxg = (j & 1) ? gxv[2][bi].y : gxv[2][bi].x;
                const float gxo = (j & 1) ? gxv[3][bi].y : gxv[3][bi].x;
                const float mk  = bi ? mk1 : mk0;
                float ig = sigf(acc[0][j] + gxi);
                float fg = sigf(acc[1][j] + gxF);
                float tg = tanhf(acc[2][j] + gxg);
                float og = sigf(acc[3][j] + gxo);
                float cn = (fg * creg[j] + ig * tg) * mk;
                hn[j] = og * tanhf(cn) * mk;
                creg[j] = cn;
            }
            const size_t ob = (size_t)t * (BATCH * D2H) + dir * HID + hcol;
            __stcg((float2*)&outcat[ob + (size_t)b0 * D2H], make_float2(hn[0], hn[1]));
            __stcg((float2*)&outcat[ob + (size_t)b1 * D2H], make_float2(hn[2], hn[3]));

            __nv_bfloat16* dhi = g_hbf[dir][(s & 1) ^ 1][0];
            __nv_bfloat16* dlo = g_hbf[dir][(s & 1) ^ 1][1];
            #pragma unroll
            for (int half = 0; half < 2; half++) {
                float v0 = hn[half * 2], v1 = hn[half * 2 + 1];
                __nv_bfloat16 h0 = __float2bfloat16(v0), h1 = __float2bfloat16(v1);
                __nv_bfloat16 l0 = __float2bfloat16(v0 - __bfloat162float(h0));
                __nv_bfloat16 l1 = __float2bfloat16(v1 - __bfloat162float(h1));
                const int bb = half ? b1 : b0;
                __nv_bfloat162 ph; ph.x = h0; ph.y = h1;
                __nv_bfloat162 pl; pl.x = l0; pl.y = l1;
                __stcg((uint32_t*)&dhi[bb * HID + hcol], *(uint32_t*)&ph);
                __stcg((uint32_t*)&dlo[bb * HID + hcol], *(uint32_t*)&pl);
            }
        }

        __threadfence();
        __syncthreads();
        if (tid == 0) {
            atomicAdd(&g_bar[dir], 1u);
            const unsigned target = (unsigned)NBLK_DIR * (unsigned)(s + 1);
            volatile unsigned* pb = &g_bar[dir];
            while (*pb < target) __nanosleep(32);
        }
        __syncthreads();
    }

    if (kh == 0) {
        *(float2*)&g_c[dir][b0 * HID + hcol] = make_float2(creg[0], creg[1]);
        *(float2*)&g_c[dir][b1 * HID + hcol] = make_float2(creg[2], creg[3]);
    }
}

// ---------------- small state kernels ----------------
__global__ void init_states_kernel(const float* __restrict__ f_init,
                                   const float* __restrict__ b_init, int layer)
{
    int idx = blockIdx.x * blockDim.x + threadIdx.x;
    if (idx < 2 && blockIdx.x == 0) g_bar[idx] = 0;
    if (idx >= BATCH * HID) return;
    int j = idx & (HID - 1);
    float fv = f_init[layer * 2 * HID + j];
    float bv = b_init[layer * 2 * HID + j];
    __nv_bfloat16 fh = __float2bfloat16(fv);
    __nv_bfloat16 bh = __float2bfloat16(bv);
    g_hbf[0][0][0][idx] = fh;
    g_hbf[0][0][1][idx] = __float2bfloat16(fv - __bfloat162float(fh));
    g_hbf[1][0][0][idx] = bh;
    g_hbf[1][0][1][idx] = __float2bfloat16(bv - __bfloat162float(bh));
}

// final h comes from the cat buffer rows (t=255 fwd half, t=0 bwd half)
__global__ void copy_states_kernel(float* __restrict__ hn, float* __restrict__ cn,
                                   int layer, int catSel)
{
    int idx = blockIdx.x * blockDim.x + threadIdx.x;
    if (idx >= BATCH * HID) return;
    int b = idx >> 9, j = idx & (HID - 1);
    const float* cat = sel_cbuf(catSel, nullptr);
    hn[(size_t)(2 * layer + 0) * BATCH * HID + idx] =
        cat[(size_t)(T_SEQ - 1) * (BATCH * D2H) + (size_t)b * D2H + j];
    hn[(size_t)(2 * layer + 1) * BATCH * HID + idx] =
        cat[(size_t)b * D2H + HID + j];
    cn[(size_t)(2 * layer + 0) * BATCH * HID + idx] = g_c[0][idx];
    cn[(size_t)(2 * layer + 1) * BATCH * HID + idx] = g_c[1][idx];
}

// ---------------- launcher ----------------
extern "C" void kernel_launch(void* const* d_in, const int* in_sizes, int n_in,
                              void* d_out, int out_size)
{
    (void)in_sizes; (void)n_in; (void)out_size;
    const float* x          = (const float*)d_in[0];
    const float* masks      = (const float*)d_in[1];
    const float* f_Wih0     = (const float*)d_in[2];
    const float* f_Wih_rest = (const float*)d_in[3];
    const float* f_Whh      = (const float*)d_in[4];
    const float* f_b        = (const float*)d_in[5];
    const float* b_Wih0     = (const float*)d_in[6];
    const float* b_Wih_rest = (const float*)d_in[7];
    const float* b_Whh      = (const float*)d_in[8];
    const float* b_b        = (const float*)d_in[9];
    const float* f_init     = (const float*)d_in[10];
    const float* b_init     = (const float*)d_in[11];
    const float* proj_W     = (const float*)d_in[12];
    const float* proj_b     = (const float*)d_in[13];

    float* out = (float*)d_out;                       // [T,B,2H]
    float* hn  = out + (size_t)MR * D2H;              // [6,B,H]
    float* cn  = hn + (size_t)6 * BATCH * HID;        // [6,B,H]

    cudaFuncSetAttribute(pers_lstm2,
                         cudaFuncAttributeMaxDynamicSharedMemorySize, PERS2_SMEM);
    cudaFuncSetAttribute(mma_gemm<0>,
                         cudaFuncAttributeMaxDynamicSharedMemorySize, MG_SMEM);
    cudaFuncSetAttribute(mma_gemm<1>,
                         cudaFuncAttributeMaxDynamicSharedMemorySize, MG_SMEM);

    const int layerInSel[3]  = { 0, 1, 3 };   // x, bufA, bufC
    const int catSel[3]      = { 1, 2, 1 };   // bufA, bufB, bufA
    const int Kin[3]         = { 512, 1024, 1024 };

    for (int layer = 0; layer < 3; layer++) {
        const int K = Kin[layer];
        init_states_kernel<<<128, 256>>>(f_init, b_init, layer);

        // ---- split-convert gate GEMM operands ----
        split_convert<<<1024, 256>>>((layer == 0) ? x : nullptr, layerInSel[layer],
                                     0, 0, ((size_t)MR * K) / 4);
        const float* Wf = (layer == 0) ? f_Wih0 : f_Wih_rest + (size_t)(layer - 1) * G4H * D2H;
        const float* Wb = (layer == 0) ? b_Wih0 : b_Wih_rest + (size_t)(layer - 1) * G4H * D2H;
        split_convert<<<512, 256>>>(Wf, 0, 1, 0,                 ((size_t)G4H * K) / 4);
        split_convert<<<512, 256>>>(Wb, 0, 1, (size_t)G4H * K,   ((size_t)G4H * K) / 4);

        // ---- gate pre-activations via tensor-core GEMM ----
        mma_gemm<0><<<dim3(G4H / 128, MR / 128, 2), 256, MG_SMEM>>>(
            f_b + (size_t)layer * G4H, b_b + (size_t)layer * G4H,
            nullptr, 4 /*gxf*/, nullptr, 5 /*gxb*/,
            nullptr, 0, nullptr, 0,
            G4H, K);

        // ---- recurrence (tensor-core persistent) ----
        const float* Whf = f_Whh + (size_t)layer * G4H * HID;
        const float* Whb = b_Whh + (size_t)layer * G4H * HID;
        pers_lstm2<<<dim3(NBLK_DIR, 2), 256, PERS2_SMEM>>>(
            Whf, Whb, masks, f_init, b_init, layer, catSel[layer], nullptr);

        copy_states_kernel<<<128, 256>>>(hn, cn, layer, catSel[layer]);

        // ---- highway projection ----
        if (layer > 0) {
            split_convert<<<1024, 256>>>(nullptr, catSel[layer], 0, 0, ((size_t)MR * D2H) / 4);
            split_convert<<<512, 256>>>(proj_W + (size_t)(layer - 1) * D2H * D2H, 0,
                                        1, 0, ((size_t)D2H * D2H) / 4);
            mma_gemm<1><<<dim3(D2H / 128, MR / 128, 1), 256, MG_SMEM>>>(
                proj_b + (size_t)(layer - 1) * D2H, nullptr,
                (layer == 2) ? out : nullptr, (layer == 1) ? 3 : 0,
                nullptr, 0,
                nullptr, catSel[layer],
                nullptr, layerInSel[layer],
                D2H, D2H);
        }
    }
}